// round 7
// baseline (speedup 1.0000x reference)
#include <cuda_runtime.h>
#include <cstdint>
#include <math.h>

#define N_NODES 10000
#define E_EDGES 640000
#define DIM     128
#define HEADS   4
#define TILE    32

// device globals are zero-initialized at module load; kernels below re-zero
// what they consume so every kernel_launch call sees identical initial state.
__device__ float g_wt[N_NODES * 512];    // w-tilde [n][h][128], scale folded
__device__ float g_c[N_NODES * HEADS];   // score const per (n,h), scale folded
__device__ float g_S[N_NODES * 512];     // raw weighted v sums  (self-cleaned by k_vproj)
__device__ float g_agg[N_NODES * DIM];
__device__ float g_den[N_NODES * HEADS]; // self-cleaned by k_vproj
__device__ int   g_cnt[N_NODES];         // self-cleaned by k_scan
__device__ int   g_cur[N_NODES];
__device__ int   g_perm[E_EDGES];

// inline edge_index dtype detect: valid int64 dsts (<10000) have zero high words.
// int32 data read as int64 has a nonzero high half w.p. 1-1e-4 per word; OR of 8
// words -> P(misdetect) ~ 1e-32.
__device__ __forceinline__ int detect32(const void* ei) {
    const long long* p = (const long long*)ei;
    long long x = 0;
    #pragma unroll
    for (int i = 0; i < 8; i++) x |= p[i];
    return (((unsigned long long)x) >> 32) != 0ull;
}
__device__ __forceinline__ int dst_at(const void* ei, int e, int is32) {
    return is32 ? ((const int*)ei)[e] : (int)((const long long*)ei)[e];
}

__device__ __forceinline__ void cp16(uint32_t sdst, const void* gsrc) {
    asm volatile("cp.async.cg.shared.global [%0], [%1], 16;" :: "r"(sdst), "l"(gsrc));
}

// ---------------- launch 0: fused qw (blocks [0,qwBlocks)) + hist (rest) ----------------
__global__ __launch_bounds__(256) void k_setup(const float* __restrict__ X,
                                               const float* __restrict__ Wq,
                                               const float* __restrict__ bq,
                                               const float* __restrict__ Wk,
                                               const float* __restrict__ bk,
                                               const void* __restrict__ ei,
                                               int n, int E, int qwBlocks) {
    if ((int)blockIdx.x >= qwBlocks) {
        // ---- histogram part ----
        __shared__ int s32;
        if (threadIdx.x == 0) s32 = detect32(ei);
        __syncthreads();
        int e = (blockIdx.x - qwBlocks) * blockDim.x + threadIdx.x;
        if (e < E) atomicAdd(&g_cnt[dst_at(ei, e, s32)], 1);
        return;
    }
    // ---- qw part: q-projection (block-local) -> w_tilde + c ----
    extern __shared__ float sw[];
    float* Ws = sw;                 // [128][132]
    float* As = sw + 128 * 132;     // [32][132]
    float* qs = As + 32 * 132;      // [32][132]
    int tid = threadIdx.x;
    int row0 = blockIdx.x * 32;

    for (int i = tid; i < DIM * DIM; i += 256) Ws[(i >> 7) * 132 + (i & 127)] = Wq[i];
    for (int i = tid; i < 32 * DIM; i += 256) {
        int r = i >> 7, c = i & 127;
        int gr = row0 + r;
        As[r * 132 + c] = (gr < n) ? X[gr * DIM + c] : 0.f;
    }
    __syncthreads();

    int cg = (tid & 31) * 4, rg = (tid >> 5) * 4;
    float acc[4][4] = {};
    #pragma unroll 8
    for (int d = 0; d < DIM; d++) {
        float4 w = *(float4*)&Ws[d * 132 + cg];
        float a0 = As[(rg + 0) * 132 + d];
        float a1 = As[(rg + 1) * 132 + d];
        float a2 = As[(rg + 2) * 132 + d];
        float a3 = As[(rg + 3) * 132 + d];
        acc[0][0] += a0 * w.x; acc[0][1] += a0 * w.y; acc[0][2] += a0 * w.z; acc[0][3] += a0 * w.w;
        acc[1][0] += a1 * w.x; acc[1][1] += a1 * w.y; acc[1][2] += a1 * w.z; acc[1][3] += a1 * w.w;
        acc[2][0] += a2 * w.x; acc[2][1] += a2 * w.y; acc[2][2] += a2 * w.z; acc[2][3] += a2 * w.w;
        acc[3][0] += a3 * w.x; acc[3][1] += a3 * w.y; acc[3][2] += a3 * w.z; acc[3][3] += a3 * w.w;
    }
    float4 bb = *(const float4*)&bq[cg];
    #pragma unroll
    for (int rr = 0; rr < 4; rr++) {
        qs[(rg + rr) * 132 + cg + 0] = acc[rr][0] + bb.x;
        qs[(rg + rr) * 132 + cg + 1] = acc[rr][1] + bb.y;
        qs[(rg + rr) * 132 + cg + 2] = acc[rr][2] + bb.z;
        qs[(rg + rr) * 132 + cg + 3] = acc[rr][3] + bb.w;
    }
    __syncthreads();

    for (int i = tid; i < DIM * DIM; i += 256) Ws[(i >> 7) * 132 + (i & 127)] = Wk[i];
    __syncthreads();

    const float scale = 0.17677669529663689f;  // 1/sqrt(32)
    int nl = tid >> 3, g = tid & 7;
    int node = row0 + nl;
    if (g < 4 && node < n) {
        int h = g;
        float cc = 0.f;
        #pragma unroll 8
        for (int d = 0; d < 32; d++) cc += qs[nl * 132 + h * 32 + d] * __ldg(&bk[h * 32 + d]);
        g_c[node * 4 + h] = cc * scale;
    }
    for (int kk = 0; kk < 16; kk++) {
        int k = kk * 8 + g;
        #pragma unroll
        for (int h = 0; h < 4; h++) {
            float acc2 = 0.f;
            #pragma unroll 8
            for (int d = 0; d < 32; d++)
                acc2 += Ws[k * 132 + h * 32 + d] * qs[nl * 132 + h * 32 + d];
            if (node < n) g_wt[node * 512 + h * 128 + k] = acc2 * scale;
        }
    }
}

// ---------------- launch 1: scan (+ self-clean g_cnt) ----------------
__global__ __launch_bounds__(1024) void k_scan(int n) {
    __shared__ int ws[32];
    int t = threadIdx.x, lane = t & 31, wd = t >> 5;
    int per = (n + 1023) / 1024;
    int base = t * per;
    int s = 0;
    for (int i = 0; i < per; i++) {
        int idx = base + i;
        if (idx < n) s += g_cnt[idx];
    }
    int incl = s;
    #pragma unroll
    for (int off = 1; off < 32; off <<= 1) {
        int y = __shfl_up_sync(0xffffffffu, incl, off);
        if (lane >= off) incl += y;
    }
    if (lane == 31) ws[wd] = incl;
    __syncthreads();
    if (wd == 0) {
        int v = ws[lane];
        int iv = v;
        #pragma unroll
        for (int off = 1; off < 32; off <<= 1) {
            int y = __shfl_up_sync(0xffffffffu, iv, off);
            if (lane >= off) iv += y;
        }
        ws[lane] = iv - v;
    }
    __syncthreads();
    int run = ws[wd] + incl - s;
    for (int i = 0; i < per; i++) {
        int idx = base + i;
        if (idx < n) {
            int v = g_cnt[idx];
            g_cur[idx] = run;
            run += v;
            g_cnt[idx] = 0;   // self-clean for next call
        }
    }
}

// ---------------- launch 2: scatter ----------------
__global__ void k_scatter(const void* __restrict__ ei, int E) {
    __shared__ int s32;
    if (threadIdx.x == 0) s32 = detect32(ei);
    __syncthreads();
    int e = blockIdx.x * blockDim.x + threadIdx.x;
    if (e < E) {
        int pos = atomicAdd(&g_cur[dst_at(ei, e, s32)], 1);
        g_perm[pos] = e;
    }
}

// ---------------- launch 3 (PROFILED): fused edge kernel ----------------
#define KB_B(p)  ((p) * 16896)
#define VB_B(p)  (33792 + (p) * 16896)
#define DT_B(p)  (67584 + (p) * 128)
#define EXS_B    67840
#define SMEM_E   68608

__device__ __forceinline__ void prefetch32(char* sm, int p, const float* __restrict__ ke,
                                           const float* __restrict__ ve,
                                           const void* __restrict__ ei,
                                           int tile, int E, int tid) {
    int half = tid >> 8;            // 0: k, 1: v
    int r = (tid >> 3) & 31;        // row 0..31 (8 threads per row)
    int q = tid & 7;                // 64B chunk
    int gi = tile * TILE + r;
    if (gi >= E) gi = E - 1;
    int pe = g_perm[gi];
    const float* src = (half ? ve : ke) + (size_t)pe * DIM + q * 16;
    uint32_t sd = (uint32_t)__cvta_generic_to_shared(
        sm + (half ? VB_B(p) : KB_B(p)) + (r * 132 + q * 16) * 4);
    #pragma unroll
    for (int j = 0; j < 4; j++) cp16(sd + j * 16, (const char*)src + j * 16);
    if (tid < TILE) {
        int gi2 = tile * TILE + tid;
        if (gi2 >= E) gi2 = E - 1;
        int is32 = detect32(ei);
        ((int*)(sm + DT_B(p)))[tid] = dst_at(ei, g_perm[gi2], is32);
    }
}

__global__ __launch_bounds__(512, 2) void k_edge(const float* __restrict__ ke,
                                                 const float* __restrict__ ve,
                                                 const void* __restrict__ ei,
                                                 int E, int ntiles) {
    extern __shared__ char sm[];
    float* exs = (float*)(sm + EXS_B);
    int tid = threadIdx.x, lane = tid & 31, w = tid >> 5;
    int STRIDE = gridDim.x, bid = blockIdx.x;

    if (bid < ntiles) prefetch32(sm, 0, ke, ve, ei, bid, E, tid);
    asm volatile("cp.async.commit_group;");

    int par = 0;
    for (int t = bid; t < ntiles; t += STRIDE, par ^= 1) {
        int nt = t + STRIDE;
        if (nt < ntiles) prefetch32(sm, par ^ 1, ke, ve, ei, nt, E, tid);
        asm volatile("cp.async.commit_group;");
        asm volatile("cp.async.wait_group 1;");
        __syncthreads();   // tile t buffers + dt visible

        const float* kb = (const float*)(sm + KB_B(par));
        const int*   dt = (const int*)(sm + DT_B(par));

        // phase A: scores (each warp: 2 edges), w-tilde register-cached per dst segment
        {
            int prevd = -1;
            float4 wv0, wv1, wv2, wv3;
            #pragma unroll
            for (int i = 0; i < 2; i++) {
                int e = w * 2 + i;
                int gi = t * TILE + e;
                int d = dt[e];
                if (d != prevd) {
                    const float* base = g_wt + (size_t)d * 512 + lane * 4;
                    wv0 = __ldg((const float4*)(base + 0));
                    wv1 = __ldg((const float4*)(base + 128));
                    wv2 = __ldg((const float4*)(base + 256));
                    wv3 = __ldg((const float4*)(base + 384));
                    prevd = d;
                }
                float4 kv = *(const float4*)&kb[e * 132 + lane * 4];
                float p0 = kv.x * wv0.x + kv.y * wv0.y + kv.z * wv0.z + kv.w * wv0.w;
                float p1 = kv.x * wv1.x + kv.y * wv1.y + kv.z * wv1.z + kv.w * wv1.w;
                float p2 = kv.x * wv2.x + kv.y * wv2.y + kv.z * wv2.z + kv.w * wv2.w;
                float p3 = kv.x * wv3.x + kv.y * wv3.y + kv.z * wv3.z + kv.w * wv3.w;
                #pragma unroll
                for (int off = 16; off >= 1; off >>= 1) {
                    p0 += __shfl_xor_sync(0xffffffffu, p0, off);
                    p1 += __shfl_xor_sync(0xffffffffu, p1, off);
                    p2 += __shfl_xor_sync(0xffffffffu, p2, off);
                    p3 += __shfl_xor_sync(0xffffffffu, p3, off);
                }
                if (lane < 4) {
                    float s = (lane == 0) ? p0 : (lane == 1) ? p1 : (lane == 2) ? p2 : p3;
                    s += __ldg(&g_c[d * 4 + lane]);
                    exs[e * 4 + lane] = (gi < E) ? __expf(s) : 0.f;
                }
            }
        }
        __syncthreads();   // exs ready

        // phase B: weighted aggregation of raw v, segmented by dst
        {
            const float* vb = (const float*)(sm + VB_B(par));
            int h = tid >> 7, c = tid & 127;
            float a = 0.f;
            #pragma unroll 4
            for (int r = 0; r < TILE; r++) {
                a += exs[r * 4 + h] * vb[r * 132 + c];
                if (r == TILE - 1 || dt[r + 1] != dt[r]) {
                    atomicAdd(&g_S[(size_t)dt[r] * 512 + h * 128 + c], a);
                    a = 0.f;
                }
            }
            if (tid < 8) {
                int hh = tid & 3, hf = tid >> 2;
                int r0 = hf * 16, r1 = r0 + 16;
                float aa = 0.f;
                for (int r = r0; r < r1; r++) {
                    aa += exs[r * 4 + hh];
                    if (r == r1 - 1 || dt[r + 1] != dt[r]) {
                        atomicAdd(&g_den[dt[r] * HEADS + hh], aa);
                        aa = 0.f;
                    }
                }
            }
        }
        __syncthreads();   // buffer reads complete before re-prefetch
    }
}

// ---------------- launch 4: agg = (S @ Wv)/den + bv  (+ self-clean g_S, g_den) ----------------
__global__ __launch_bounds__(256) void k_vproj(const float* __restrict__ Wv,
                                               const float* __restrict__ bv, int n) {
    extern __shared__ float sv[];
    float* Ws = sv;               // [128][128]
    float* Ss = sv + 128 * 128;   // [32][4][136]
    int tid = threadIdx.x;
    int row0 = blockIdx.x * 32;
    for (int i = tid; i < DIM * DIM; i += 256) Ws[i] = Wv[i];
    for (int i = tid; i < 32 * 512; i += 256) {
        int nl = i >> 9, rest = i & 511;
        int h = rest >> 7, d = rest & 127;
        int gr = row0 + nl;
        float v = 0.f;
        if (gr < n) {
            size_t idx = (size_t)gr * 512 + rest;
            v = g_S[idx];
            g_S[idx] = 0.f;   // self-clean (exclusive owner: this thread)
        }
        Ss[nl * 544 + h * 136 + d] = v;
    }
    __syncthreads();
    int cg = (tid & 31) * 4, rg = (tid >> 5) * 4;
    int h = cg >> 5;
    float acc[4][4] = {};
    #pragma unroll 8
    for (int d = 0; d < DIM; d++) {
        float4 wv = *(float4*)&Ws[d * DIM + cg];
        float a0 = Ss[(rg + 0) * 544 + h * 136 + d];
        float a1 = Ss[(rg + 1) * 544 + h * 136 + d];
        float a2 = Ss[(rg + 2) * 544 + h * 136 + d];
        float a3 = Ss[(rg + 3) * 544 + h * 136 + d];
        acc[0][0] += a0 * wv.x; acc[0][1] += a0 * wv.y; acc[0][2] += a0 * wv.z; acc[0][3] += a0 * wv.w;
        acc[1][0] += a1 * wv.x; acc[1][1] += a1 * wv.y; acc[1][2] += a1 * wv.z; acc[1][3] += a1 * wv.w;
        acc[2][0] += a2 * wv.x; acc[2][1] += a2 * wv.y; acc[2][2] += a2 * wv.z; acc[2][3] += a2 * wv.w;
        acc[3][0] += a3 * wv.x; acc[3][1] += a3 * wv.y; acc[3][2] += a3 * wv.z; acc[3][3] += a3 * wv.w;
    }
    float4 bb = *(const float4*)&bv[cg];
    #pragma unroll
    for (int rr = 0; rr < 4; rr++) {
        int gr = row0 + rg + rr;
        if (gr < n) {
            float den = g_den[gr * HEADS + h];
            float4 o;
            if (den > 0.f) {
                float inv = 1.f / den;
                o = make_float4(acc[rr][0] * inv + bb.x, acc[rr][1] * inv + bb.y,
                                acc[rr][2] * inv + bb.z, acc[rr][3] * inv + bb.w);
            } else {
                o = make_float4(0.f, 0.f, 0.f, 0.f);
            }
            *(float4*)&g_agg[gr * DIM + cg] = o;
        }
    }
    __syncthreads();   // all den reads done (block owns nodes row0..row0+31)
    for (int i = tid; i < 32 * HEADS; i += 256) {
        int gr = row0 + (i >> 2);
        if (gr < n) g_den[gr * HEADS + (i & 3)] = 0.f;   // self-clean
    }
}

// ---------------- launch 5: out = agg @ Wo + bo ----------------
__global__ __launch_bounds__(256) void k_out(const float* __restrict__ W,
                                             const float* __restrict__ b,
                                             float* __restrict__ Y, int n) {
    extern __shared__ float so[];
    float* Ws = so;
    float* As = so + DIM * DIM;
    int tid = threadIdx.x;
    for (int i = tid; i < DIM * DIM; i += 256) Ws[i] = W[i];
    int row0 = blockIdx.x * 32;
    for (int i = tid; i < 32 * DIM; i += 256) {
        int r = i >> 7, c = i & 127;
        int gr = row0 + r;
        As[r * 132 + c] = (gr < n) ? g_agg[gr * DIM + c] : 0.f;
    }
    __syncthreads();
    int cg = (tid & 31) * 4, rg = (tid >> 5) * 4;
    float acc[4][4] = {};
    #pragma unroll 8
    for (int d = 0; d < DIM; d++) {
        float4 w = *(float4*)&Ws[d * DIM + cg];
        float a0 = As[(rg + 0) * 132 + d];
        float a1 = As[(rg + 1) * 132 + d];
        float a2 = As[(rg + 2) * 132 + d];
        float a3 = As[(rg + 3) * 132 + d];
        acc[0][0] += a0 * w.x; acc[0][1] += a0 * w.y; acc[0][2] += a0 * w.z; acc[0][3] += a0 * w.w;
        acc[1][0] += a1 * w.x; acc[1][1] += a1 * w.y; acc[1][2] += a1 * w.z; acc[1][3] += a1 * w.w;
        acc[2][0] += a2 * w.x; acc[2][1] += a2 * w.y; acc[2][2] += a2 * w.z; acc[2][3] += a2 * w.w;
        acc[3][0] += a3 * w.x; acc[3][1] += a3 * w.y; acc[3][2] += a3 * w.z; acc[3][3] += a3 * w.w;
    }
    float4 bb = *(const float4*)&b[cg];
    #pragma unroll
    for (int rr = 0; rr < 4; rr++) {
        int gr = row0 + rg + rr;
        if (gr < n) {
            float4 o = make_float4(acc[rr][0] + bb.x, acc[rr][1] + bb.y,
                                   acc[rr][2] + bb.z, acc[rr][3] + bb.w);
            *(float4*)&Y[gr * DIM + cg] = o;
        }
    }
}

extern "C" void kernel_launch(void* const* d_in, const int* in_sizes, int n_in,
                              void* d_out, int out_size) {
    const float* q_nodes = (const float*)d_in[0];
    const float* k_edges = (const float*)d_in[1];
    const float* v_edges = (const float*)d_in[2];
    const float* Wq = (const float*)d_in[3];
    const float* bq = (const float*)d_in[4];
    const float* Wk = (const float*)d_in[5];
    const float* bk = (const float*)d_in[6];
    const float* Wv = (const float*)d_in[7];
    const float* bv = (const float*)d_in[8];
    const float* Wo = (const float*)d_in[9];
    const float* bo = (const float*)d_in[10];
    const void*  ei = (const void*)d_in[11];

    int N = in_sizes[0] / DIM;
    int E = in_sizes[1] / DIM;
    int ntiles = (E + TILE - 1) / TILE;

    int dev = 0, sms = 148;
    cudaGetDevice(&dev);
    cudaDeviceGetAttribute(&sms, cudaDevAttrMultiProcessorCount, dev);

    const int qwBlocks = (N + 31) / 32;
    const int histBlocks = (E + 255) / 256;
    const int smem_qw = (128 * 132 + 32 * 132 + 32 * 132) * (int)sizeof(float);
    const int smem_vp = (128 * 128 + 32 * 544) * (int)sizeof(float);
    const int smem_sm = (DIM * DIM + 32 * 132) * (int)sizeof(float);
    cudaFuncSetAttribute(k_setup, cudaFuncAttributeMaxDynamicSharedMemorySize, smem_qw);
    cudaFuncSetAttribute(k_vproj, cudaFuncAttributeMaxDynamicSharedMemorySize, smem_vp);
    cudaFuncSetAttribute(k_out, cudaFuncAttributeMaxDynamicSharedMemorySize, smem_sm);
    cudaFuncSetAttribute(k_edge, cudaFuncAttributeMaxDynamicSharedMemorySize, SMEM_E);

    k_setup<<<qwBlocks + histBlocks, 256, smem_qw>>>(q_nodes, Wq, bq, Wk, bk, ei, N, E, qwBlocks);
    k_scan<<<1, 1024>>>(N);
    k_scatter<<<(E + 255) / 256, 256>>>(ei, E);
    k_edge<<<2 * sms, 512, SMEM_E>>>(k_edges, v_edges, ei, E, ntiles);   // idx 3 -> profiled
    k_vproj<<<(N + 31) / 32, 256, smem_vp>>>(Wv, bv, N);
    k_out<<<(N + 31) / 32, 256, smem_sm>>>(Wo, bo, (float*)d_out, N);
}

// round 8
// speedup vs baseline: 1.3136x; 1.3136x over previous
#include <cuda_runtime.h>
#include <cstdint>
#include <math.h>

#define N_NODES 10000
#define E_EDGES 640000
#define DIM     128
#define HEADS   4

// device globals zero-init at load; consumers re-zero what they read so every
// kernel_launch call sees identical initial state.
__device__ float g_M[128 * 512];         // M[c][h*128+k]
__device__ float g_B[512];               // B[h*128+k]
__device__ float g_Mb[128 * 4];          // Mb[c][h]
__device__ float g_cb[4];
__device__ float g_wt[N_NODES * 512];    // w-tilde [n][h*128+k], scale folded
__device__ float g_c[N_NODES * HEADS];   // score const, scale folded
__device__ float g_S[N_NODES * 512];     // raw weighted v sums (self-cleaned by k_vproj)
__device__ float g_agg[N_NODES * DIM];
__device__ float g_den[N_NODES * HEADS]; // self-cleaned by k_vproj
__device__ int   g_cnt[N_NODES];         // self-cleaned by k_scan
__device__ int   g_cur[N_NODES];
__device__ int   g_perm[E_EDGES];

// edge_index dtype detect: int64 dsts (<10000) have zero high words.
__device__ __forceinline__ int detect32(const void* ei) {
    const long long* p = (const long long*)ei;
    long long x = 0;
    #pragma unroll
    for (int i = 0; i < 8; i++) x |= p[i];
    return (((unsigned long long)x) >> 32) != 0ull;
}
__device__ __forceinline__ int dst_at(const void* ei, int e, int is32) {
    return is32 ? ((const int*)ei)[e] : (int)((const long long*)ei)[e];
}

// ---------------- launch 0: k_prep — build M, B, Mb, cb ----------------
// grid 32 blocks x 256 thr; block b owns k in [4b, 4b+4)
__global__ __launch_bounds__(256) void k_prep(const float* __restrict__ Wq,
                                              const float* __restrict__ bq,
                                              const float* __restrict__ Wk,
                                              const float* __restrict__ bk) {
    extern __shared__ float sp[];
    float* Wqs = sp;             // [128][132]
    float* Wks = sp + 128 * 132; // [4][128]
    int tid = threadIdx.x, b = blockIdx.x;
    for (int i = tid; i < 128 * 128; i += 256) Wqs[(i >> 7) * 132 + (i & 127)] = Wq[i];
    for (int i = tid; i < 4 * 128; i += 256) Wks[i] = Wk[(b * 4 + (i >> 7)) * 128 + (i & 127)];
    __syncthreads();

    int c = tid & 127, kp = tid >> 7;  // kp 0/1 -> k_local {2kp, 2kp+1}
    #pragma unroll
    for (int h = 0; h < 4; h++) {
        float wq[32];
        #pragma unroll
        for (int d = 0; d < 32; d++) wq[d] = Wqs[c * 132 + h * 32 + d];
        #pragma unroll
        for (int j = 0; j < 2; j++) {
            int kl = 2 * kp + j;
            float s = 0.f;
            #pragma unroll
            for (int d = 0; d < 32; d++) s += wq[d] * Wks[kl * 128 + h * 32 + d];
            g_M[c * 512 + h * 128 + b * 4 + kl] = s;
        }
    }
    if (tid < 16) {
        int kl = tid >> 2, h = tid & 3;
        float s = 0.f;
        #pragma unroll
        for (int d = 0; d < 32; d++) s += __ldg(&bq[h * 32 + d]) * Wks[kl * 128 + h * 32 + d];
        g_B[h * 128 + b * 4 + kl] = s;
    }
    if (b == 0) {
        int hp = tid >> 7;
        #pragma unroll
        for (int j = 0; j < 2; j++) {
            int h = 2 * hp + j;
            float s = 0.f;
            #pragma unroll
            for (int d = 0; d < 32; d++) s += Wqs[c * 132 + h * 32 + d] * __ldg(&bk[h * 32 + d]);
            g_Mb[c * 4 + h] = s;
        }
        if (tid < 4) {
            float s = 0.f;
            #pragma unroll
            for (int d = 0; d < 32; d++) s += __ldg(&bq[tid * 32 + d]) * __ldg(&bk[tid * 32 + d]);
            g_cb[tid] = s;
        }
    }
}

// ---------------- launch 1: hist ----------------
__global__ void k_hist(const void* __restrict__ ei, int E) {
    __shared__ int s32;
    if (threadIdx.x == 0) s32 = detect32(ei);
    __syncthreads();
    int e = blockIdx.x * blockDim.x + threadIdx.x;
    if (e < E) atomicAdd(&g_cnt[dst_at(ei, e, s32)], 1);
}

// ---------------- launch 2: scan (+ self-clean g_cnt) ----------------
__global__ __launch_bounds__(1024) void k_scan(int n) {
    __shared__ int ws[32];
    int t = threadIdx.x, lane = t & 31, wd = t >> 5;
    int per = (n + 1023) / 1024;
    int base = t * per;
    int s = 0;
    for (int i = 0; i < per; i++) {
        int idx = base + i;
        if (idx < n) s += g_cnt[idx];
    }
    int incl = s;
    #pragma unroll
    for (int off = 1; off < 32; off <<= 1) {
        int y = __shfl_up_sync(0xffffffffu, incl, off);
        if (lane >= off) incl += y;
    }
    if (lane == 31) ws[wd] = incl;
    __syncthreads();
    if (wd == 0) {
        int v = ws[lane];
        int iv = v;
        #pragma unroll
        for (int off = 1; off < 32; off <<= 1) {
            int y = __shfl_up_sync(0xffffffffu, iv, off);
            if (lane >= off) iv += y;
        }
        ws[lane] = iv - v;
    }
    __syncthreads();
    int run = ws[wd] + incl - s;
    for (int i = 0; i < per; i++) {
        int idx = base + i;
        if (idx < n) {
            int v = g_cnt[idx];
            g_cur[idx] = run;
            run += v;
            g_cnt[idx] = 0;
        }
    }
}

// ---------------- launch 3 (PROFILED): k_wt — [wt|c] = X @ [M|Mb] + [B|cb], scaled ----------------
// grid (ceil(n/32), 5): by 0..3 -> 128 wt cols; by 4 -> the 4 c cols
__global__ __launch_bounds__(256) void k_wt(const float* __restrict__ X, int n) {
    extern __shared__ float sv[];
    float* Ms = sv;               // [128][132] (or Mb[128][4] for by==4)
    float* As = sv + 128 * 132;   // [32][132]
    int tid = threadIdx.x;
    int row0 = blockIdx.x * 32;
    int by = blockIdx.y;
    const float scale = 0.17677669529663689f;  // 1/sqrt(32)

    for (int i = tid; i < 32 * DIM; i += 256) {
        int r = i >> 7, c = i & 127;
        int gr = row0 + r;
        As[r * 132 + c] = (gr < n) ? X[gr * DIM + c] : 0.f;
    }
    if (by == 4) {
        for (int i = tid; i < 512; i += 256) Ms[i] = g_Mb[i];
        __syncthreads();
        if (tid < 128) {
            int nl = tid >> 2, h = tid & 3;
            float s = 0.f;
            #pragma unroll 8
            for (int c = 0; c < 128; c++) s += As[nl * 132 + c] * Ms[c * 4 + h];
            int node = row0 + nl;
            if (node < n) g_c[node * 4 + h] = (s + g_cb[h]) * scale;
        }
        return;
    }
    for (int i = tid; i < 128 * 128; i += 256) {
        int r = i >> 7, c = i & 127;
        Ms[r * 132 + c] = g_M[r * 512 + by * 128 + c];
    }
    __syncthreads();

    int cg = (tid & 31) * 4, rg = (tid >> 5) * 4;
    float acc[4][4] = {};
    #pragma unroll 8
    for (int d = 0; d < DIM; d++) {
        float4 w = *(float4*)&Ms[d * 132 + cg];
        float a0 = As[(rg + 0) * 132 + d];
        float a1 = As[(rg + 1) * 132 + d];
        float a2 = As[(rg + 2) * 132 + d];
        float a3 = As[(rg + 3) * 132 + d];
        acc[0][0] += a0 * w.x; acc[0][1] += a0 * w.y; acc[0][2] += a0 * w.z; acc[0][3] += a0 * w.w;
        acc[1][0] += a1 * w.x; acc[1][1] += a1 * w.y; acc[1][2] += a1 * w.z; acc[1][3] += a1 * w.w;
        acc[2][0] += a2 * w.x; acc[2][1] += a2 * w.y; acc[2][2] += a2 * w.z; acc[2][3] += a2 * w.w;
        acc[3][0] += a3 * w.x; acc[3][1] += a3 * w.y; acc[3][2] += a3 * w.z; acc[3][3] += a3 * w.w;
    }
    float4 bb = *(const float4*)&g_B[by * 128 + cg];
    #pragma unroll
    for (int rr = 0; rr < 4; rr++) {
        int gr = row0 + rg + rr;
        if (gr < n) {
            float4 o = make_float4((acc[rr][0] + bb.x) * scale, (acc[rr][1] + bb.y) * scale,
                                   (acc[rr][2] + bb.z) * scale, (acc[rr][3] + bb.w) * scale);
            *(float4*)&g_wt[(size_t)gr * 512 + by * 128 + cg] = o;
        }
    }
}

// ---------------- launch 4: scatter ----------------
__global__ void k_scatter(const void* __restrict__ ei, int E) {
    __shared__ int s32;
    if (threadIdx.x == 0) s32 = detect32(ei);
    __syncthreads();
    int e = blockIdx.x * blockDim.x + threadIdx.x;
    if (e < E) {
        int pos = atomicAdd(&g_cur[dst_at(ei, e, s32)], 1);
        g_perm[pos] = e;
    }
}

// ---------------- launch 5: k_edge — register streaming, warp per edge ----------------
__device__ __forceinline__ void flush_seg(int d, int lane, float4& a0, float4& a1,
                                          float4& a2, float4& a3, float4& ad) {
    float* S = g_S + (size_t)d * 512 + lane * 4;
    atomicAdd(S + 0,   a0.x); atomicAdd(S + 1,   a0.y); atomicAdd(S + 2,   a0.z); atomicAdd(S + 3,   a0.w);
    atomicAdd(S + 128, a1.x); atomicAdd(S + 129, a1.y); atomicAdd(S + 130, a1.z); atomicAdd(S + 131, a1.w);
    atomicAdd(S + 256, a2.x); atomicAdd(S + 257, a2.y); atomicAdd(S + 258, a2.z); atomicAdd(S + 259, a2.w);
    atomicAdd(S + 384, a3.x); atomicAdd(S + 385, a3.y); atomicAdd(S + 386, a3.z); atomicAdd(S + 387, a3.w);
    if (lane < 4) {
        float dv = (lane == 0) ? ad.x : (lane == 1) ? ad.y : (lane == 2) ? ad.z : ad.w;
        atomicAdd(&g_den[d * 4 + lane], dv);
    }
    a0 = a1 = a2 = a3 = make_float4(0.f, 0.f, 0.f, 0.f);
    ad = make_float4(0.f, 0.f, 0.f, 0.f);
}

__global__ __launch_bounds__(256) void k_edge(const float* __restrict__ ke,
                                              const float* __restrict__ ve,
                                              const void* __restrict__ ei, int E) {
    __shared__ int s32s;
    if (threadIdx.x == 0) s32s = detect32(ei);
    __syncthreads();
    int is32 = s32s;
    int lane = threadIdx.x & 31;
    int gw = (blockIdx.x * blockDim.x + threadIdx.x) >> 5;
    int base = gw * 64;
    if (base >= E) return;
    int cnt = min(64, E - base);

    int pe_l[2], d_l[2];
    #pragma unroll
    for (int j = 0; j < 2; j++) {
        int idx = base + j * 32 + lane;
        if (idx < E) {
            pe_l[j] = g_perm[idx];
            d_l[j] = dst_at(ei, pe_l[j], is32);
        } else { pe_l[j] = 0; d_l[j] = -1; }
    }

    float4 a0 = make_float4(0.f, 0.f, 0.f, 0.f), a1 = a0, a2 = a0, a3 = a0, ad = a0;
    int prevd = -1;
    float4 wv0, wv1, wv2, wv3, cv;
    wv0 = wv1 = wv2 = wv3 = cv = a0;

    int pe0 = __shfl_sync(0xffffffffu, pe_l[0], 0);
    float4 kv = __ldg((const float4*)(ke + (size_t)pe0 * DIM) + lane);
    float4 vv = __ldg((const float4*)(ve + (size_t)pe0 * DIM) + lane);

    for (int i = 0; i < cnt; i++) {
        int d = __shfl_sync(0xffffffffu, d_l[i >> 5], i & 31);
        float4 kn = kv, vn = vv;
        if (i + 1 < cnt) {
            int pn = __shfl_sync(0xffffffffu, pe_l[(i + 1) >> 5], (i + 1) & 31);
            kn = __ldg((const float4*)(ke + (size_t)pn * DIM) + lane);
            vn = __ldg((const float4*)(ve + (size_t)pn * DIM) + lane);
        }
        if (d != prevd) {
            if (prevd >= 0) flush_seg(prevd, lane, a0, a1, a2, a3, ad);
            const float4* bw = (const float4*)(g_wt + (size_t)d * 512) + lane;
            wv0 = __ldg(bw); wv1 = __ldg(bw + 32); wv2 = __ldg(bw + 64); wv3 = __ldg(bw + 96);
            cv = __ldg((const float4*)(g_c + d * 4));
            prevd = d;
        }
        float p0 = kv.x * wv0.x + kv.y * wv0.y + kv.z * wv0.z + kv.w * wv0.w;
        float p1 = kv.x * wv1.x + kv.y * wv1.y + kv.z * wv1.z + kv.w * wv1.w;
        float p2 = kv.x * wv2.x + kv.y * wv2.y + kv.z * wv2.z + kv.w * wv2.w;
        float p3 = kv.x * wv3.x + kv.y * wv3.y + kv.z * wv3.z + kv.w * wv3.w;
        #pragma unroll
        for (int off = 16; off; off >>= 1) {
            p0 += __shfl_xor_sync(0xffffffffu, p0, off);
            p1 += __shfl_xor_sync(0xffffffffu, p1, off);
            p2 += __shfl_xor_sync(0xffffffffu, p2, off);
            p3 += __shfl_xor_sync(0xffffffffu, p3, off);
        }
        float e0 = __expf(p0 + cv.x);
        float e1 = __expf(p1 + cv.y);
        float e2 = __expf(p2 + cv.z);
        float e3 = __expf(p3 + cv.w);
        a0.x += e0 * vv.x; a0.y += e0 * vv.y; a0.z += e0 * vv.z; a0.w += e0 * vv.w;
        a1.x += e1 * vv.x; a1.y += e1 * vv.y; a1.z += e1 * vv.z; a1.w += e1 * vv.w;
        a2.x += e2 * vv.x; a2.y += e2 * vv.y; a2.z += e2 * vv.z; a2.w += e2 * vv.w;
        a3.x += e3 * vv.x; a3.y += e3 * vv.y; a3.z += e3 * vv.z; a3.w += e3 * vv.w;
        ad.x += e0; ad.y += e1; ad.z += e2; ad.w += e3;
        kv = kn; vv = vn;
    }
    flush_seg(prevd, lane, a0, a1, a2, a3, ad);
}

// ---------------- launch 6: agg = (S @ Wv)/den + bv (+ self-clean) ----------------
__global__ __launch_bounds__(256) void k_vproj(const float* __restrict__ Wv,
                                               const float* __restrict__ bv, int n) {
    extern __shared__ float sv[];
    float* Ws = sv;               // [128][128]
    float* Ss = sv + 128 * 128;   // [32][4][136]
    int tid = threadIdx.x;
    int row0 = blockIdx.x * 32;
    for (int i = tid; i < DIM * DIM; i += 256) Ws[i] = Wv[i];
    for (int i = tid; i < 32 * 512; i += 256) {
        int nl = i >> 9, rest = i & 511;
        int h = rest >> 7, d = rest & 127;
        int gr = row0 + nl;
        float v = 0.f;
        if (gr < n) {
            size_t idx = (size_t)gr * 512 + rest;
            v = g_S[idx];
            g_S[idx] = 0.f;
        }
        Ss[nl * 544 + h * 136 + d] = v;
    }
    __syncthreads();
    int cg = (tid & 31) * 4, rg = (tid >> 5) * 4;
    int h = cg >> 5;
    float acc[4][4] = {};
    #pragma unroll 8
    for (int d = 0; d < DIM; d++) {
        float4 wv = *(float4*)&Ws[d * DIM + cg];
        float a0 = Ss[(rg + 0) * 544 + h * 136 + d];
        float a1 = Ss[(rg + 1) * 544 + h * 136 + d];
        float a2 = Ss[(rg + 2) * 544 + h * 136 + d];
        float a3 = Ss[(rg + 3) * 544 + h * 136 + d];
        acc[0][0] += a0 * wv.x; acc[0][1] += a0 * wv.y; acc[0][2] += a0 * wv.z; acc[0][3] += a0 * wv.w;
        acc[1][0] += a1 * wv.x; acc[1][1] += a1 * wv.y; acc[1][2] += a1 * wv.z; acc[1][3] += a1 * wv.w;
        acc[2][0] += a2 * wv.x; acc[2][1] += a2 * wv.y; acc[2][2] += a2 * wv.z; acc[2][3] += a2 * wv.w;
        acc[3][0] += a3 * wv.x; acc[3][1] += a3 * wv.y; acc[3][2] += a3 * wv.z; acc[3][3] += a3 * wv.w;
    }
    float4 bb = *(const float4*)&bv[cg];
    #pragma unroll
    for (int rr = 0; rr < 4; rr++) {
        int gr = row0 + rg + rr;
        if (gr < n) {
            float den = g_den[gr * HEADS + h];
            float4 o;
            if (den > 0.f) {
                float inv = 1.f / den;
                o = make_float4(acc[rr][0] * inv + bb.x, acc[rr][1] * inv + bb.y,
                                acc[rr][2] * inv + bb.z, acc[rr][3] * inv + bb.w);
            } else {
                o = make_float4(0.f, 0.f, 0.f, 0.f);
            }
            *(float4*)&g_agg[gr * DIM + cg] = o;
        }
    }
    __syncthreads();
    for (int i = tid; i < 32 * HEADS; i += 256) {
        int gr = row0 + (i >> 2);
        if (gr < n) g_den[gr * HEADS + (i & 3)] = 0.f;
    }
}

// ---------------- launch 7: out = agg @ Wo + bo ----------------
__global__ __launch_bounds__(256) void k_out(const float* __restrict__ W,
                                             const float* __restrict__ b,
                                             float* __restrict__ Y, int n) {
    extern __shared__ float so[];
    float* Ws = so;
    float* As = so + DIM * DIM;
    int tid = threadIdx.x;
    for (int i = tid; i < DIM * DIM; i += 256) Ws[i] = W[i];
    int row0 = blockIdx.x * 32;
    for (int i = tid; i < 32 * DIM; i += 256) {
        int r = i >> 7, c = i & 127;
        int gr = row0 + r;
        As[r * 132 + c] = (gr < n) ? g_agg[gr * DIM + c] : 0.f;
    }
    __syncthreads();
    int cg = (tid & 31) * 4, rg = (tid >> 5) * 4;
    float acc[4][4] = {};
    #pragma unroll 8
    for (int d = 0; d < DIM; d++) {
        float4 w = *(float4*)&Ws[d * DIM + cg];
        float a0 = As[(rg + 0) * 132 + d];
        float a1 = As[(rg + 1) * 132 + d];
        float a2 = As[(rg + 2) * 132 + d];
        float a3 = As[(rg + 3) * 132 + d];
        acc[0][0] += a0 * w.x; acc[0][1] += a0 * w.y; acc[0][2] += a0 * w.z; acc[0][3] += a0 * w.w;
        acc[1][0] += a1 * w.x; acc[1][1] += a1 * w.y; acc[1][2] += a1 * w.z; acc[1][3] += a1 * w.w;
        acc[2][0] += a2 * w.x; acc[2][1] += a2 * w.y; acc[2][2] += a2 * w.z; acc[2][3] += a2 * w.w;
        acc[3][0] += a3 * w.x; acc[3][1] += a3 * w.y; acc[3][2] += a3 * w.z; acc[3][3] += a3 * w.w;
    }
    float4 bb = *(const float4*)&b[cg];
    #pragma unroll
    for (int rr = 0; rr < 4; rr++) {
        int gr = row0 + rg + rr;
        if (gr < n) {
            float4 o = make_float4(acc[rr][0] + bb.x, acc[rr][1] + bb.y,
                                   acc[rr][2] + bb.z, acc[rr][3] + bb.w);
            *(float4*)&Y[gr * DIM + cg] = o;
        }
    }
}

extern "C" void kernel_launch(void* const* d_in, const int* in_sizes, int n_in,
                              void* d_out, int out_size) {
    const float* q_nodes = (const float*)d_in[0];
    const float* k_edges = (const float*)d_in[1];
    const float* v_edges = (const float*)d_in[2];
    const float* Wq = (const float*)d_in[3];
    const float* bq = (const float*)d_in[4];
    const float* Wk = (const float*)d_in[5];
    const float* bk = (const float*)d_in[6];
    const float* Wv = (const float*)d_in[7];
    const float* bv = (const float*)d_in[8];
    const float* Wo = (const float*)d_in[9];
    const float* bo = (const float*)d_in[10];
    const void*  ei = (const void*)d_in[11];

    int N = in_sizes[0] / DIM;
    int E = in_sizes[1] / DIM;

    const int smem_prep = (128 * 132 + 4 * 128) * (int)sizeof(float);
    const int smem_wt   = (128 * 132 + 32 * 132) * (int)sizeof(float);
    const int smem_vp   = (128 * 128 + 32 * 544) * (int)sizeof(float);
    const int smem_out  = (DIM * DIM + 32 * 132) * (int)sizeof(float);
    cudaFuncSetAttribute(k_prep, cudaFuncAttributeMaxDynamicSharedMemorySize, smem_prep);
    cudaFuncSetAttribute(k_wt, cudaFuncAttributeMaxDynamicSharedMemorySize, smem_wt);
    cudaFuncSetAttribute(k_vproj, cudaFuncAttributeMaxDynamicSharedMemorySize, smem_vp);
    cudaFuncSetAttribute(k_out, cudaFuncAttributeMaxDynamicSharedMemorySize, smem_out);

    int nblk = (N + 31) / 32;
    int ewarps = (E + 63) / 64;          // one warp per 64 edges
    int eblocks = (ewarps + 7) / 8;      // 256 threads = 8 warps

    k_prep<<<32, 256, smem_prep>>>(Wq, bq, Wk, bk);                    // 0
    k_hist<<<(E + 255) / 256, 256>>>(ei, E);                           // 1
    k_scan<<<1, 1024>>>(N);                                            // 2
    k_wt<<<dim3(nblk, 5), 256, smem_wt>>>(q_nodes, N);                 // 3 (profiled)
    k_scatter<<<(E + 255) / 256, 256>>>(ei, E);                        // 4
    k_edge<<<eblocks, 256>>>(k_edges, v_edges, ei, E);                 // 5
    k_vproj<<<nblk, 256, smem_vp>>>(Wv, bv, N);                        // 6
    k_out<<<nblk, 256, smem_out>>>(Wo, bo, (float*)d_out, N);          // 7
}

// round 9
// speedup vs baseline: 1.3460x; 1.0247x over previous
#include <cuda_runtime.h>
#include <cstdint>
#include <math.h>

#define N_NODES 10000
#define E_EDGES 640000
#define DIM     128
#define HEADS   4

// device globals zero-init at load; consumers re-zero what they read.
__device__ float g_M[128 * 512];         // M[c][h*128+k], scale folded
__device__ float g_B[512];               // B[h*128+k], scale folded
__device__ float g_Mb[128 * 4];          // Mb[c][h], scale folded
__device__ float g_cb[4];                // scale folded
__device__ float g_wt[N_NODES * 512];    // w-tilde [n][h*128+k]
__device__ float g_c[N_NODES * HEADS];
__device__ float g_S[N_NODES * 512];     // self-cleaned by k_vproj
__device__ float g_agg[N_NODES * DIM];
__device__ float g_den[N_NODES * HEADS]; // self-cleaned by k_vproj
__device__ int   g_cnt[N_NODES];         // self-cleaned by k_scan
__device__ int   g_cur[N_NODES];
__device__ int   g_perm[E_EDGES];

__device__ __forceinline__ int detect32(const void* ei) {
    const long long* p = (const long long*)ei;
    long long x = 0;
    #pragma unroll
    for (int i = 0; i < 8; i++) x |= p[i];
    return (((unsigned long long)x) >> 32) != 0ull;
}
__device__ __forceinline__ int dst_at(const void* ei, int e, int is32) {
    return is32 ? ((const int*)ei)[e] : (int)((const long long*)ei)[e];
}

// ---------------- launch 0: prep (blocks [0,32)) + hist (rest) ----------------
__global__ __launch_bounds__(256) void k_prep_hist(const float* __restrict__ Wq,
                                                   const float* __restrict__ bq,
                                                   const float* __restrict__ Wk,
                                                   const float* __restrict__ bk,
                                                   const void* __restrict__ ei, int E) {
    const float scale = 0.17677669529663689f;  // 1/sqrt(32)
    if ((int)blockIdx.x >= 32) {
        __shared__ int s32;
        if (threadIdx.x == 0) s32 = detect32(ei);
        __syncthreads();
        int e = (blockIdx.x - 32) * blockDim.x + threadIdx.x;
        if (e < E) atomicAdd(&g_cnt[dst_at(ei, e, s32)], 1);
        return;
    }
    extern __shared__ float sp[];
    float* Wqs = sp;             // [128][132]
    float* Wks = sp + 128 * 132; // [4][128]
    int tid = threadIdx.x, b = blockIdx.x;
    for (int i = tid; i < 128 * 128; i += 256) Wqs[(i >> 7) * 132 + (i & 127)] = Wq[i];
    for (int i = tid; i < 4 * 128; i += 256) Wks[i] = Wk[(b * 4 + (i >> 7)) * 128 + (i & 127)];
    __syncthreads();

    int c = tid & 127, kp = tid >> 7;
    #pragma unroll
    for (int h = 0; h < 4; h++) {
        float wq[32];
        #pragma unroll
        for (int d = 0; d < 32; d++) wq[d] = Wqs[c * 132 + h * 32 + d];
        #pragma unroll
        for (int j = 0; j < 2; j++) {
            int kl = 2 * kp + j;
            float s = 0.f;
            #pragma unroll
            for (int d = 0; d < 32; d++) s += wq[d] * Wks[kl * 128 + h * 32 + d];
            g_M[c * 512 + h * 128 + b * 4 + kl] = s * scale;
        }
    }
    if (tid < 16) {
        int kl = tid >> 2, h = tid & 3;
        float s = 0.f;
        #pragma unroll
        for (int d = 0; d < 32; d++) s += __ldg(&bq[h * 32 + d]) * Wks[kl * 128 + h * 32 + d];
        g_B[h * 128 + b * 4 + kl] = s * scale;
    }
    if (b == 0) {
        int hp = tid >> 7;
        #pragma unroll
        for (int j = 0; j < 2; j++) {
            int h = 2 * hp + j;
            float s = 0.f;
            #pragma unroll
            for (int d = 0; d < 32; d++) s += Wqs[c * 132 + h * 32 + d] * __ldg(&bk[h * 32 + d]);
            g_Mb[c * 4 + h] = s * scale;
        }
        if (tid < 4) {
            float s = 0.f;
            #pragma unroll
            for (int d = 0; d < 32; d++) s += __ldg(&bq[tid * 32 + d]) * __ldg(&bk[tid * 32 + d]);
            g_cb[tid] = s * scale;
        }
    }
}

// ---------------- launch 1: scan (+ self-clean g_cnt) ----------------
__global__ __launch_bounds__(1024) void k_scan(int n) {
    __shared__ int ws[32];
    int t = threadIdx.x, lane = t & 31, wd = t >> 5;
    int per = (n + 1023) / 1024;
    int base = t * per;
    int s = 0;
    for (int i = 0; i < per; i++) {
        int idx = base + i;
        if (idx < n) s += g_cnt[idx];
    }
    int incl = s;
    #pragma unroll
    for (int off = 1; off < 32; off <<= 1) {
        int y = __shfl_up_sync(0xffffffffu, incl, off);
        if (lane >= off) incl += y;
    }
    if (lane == 31) ws[wd] = incl;
    __syncthreads();
    if (wd == 0) {
        int v = ws[lane];
        int iv = v;
        #pragma unroll
        for (int off = 1; off < 32; off <<= 1) {
            int y = __shfl_up_sync(0xffffffffu, iv, off);
            if (lane >= off) iv += y;
        }
        ws[lane] = iv - v;
    }
    __syncthreads();
    int run = ws[wd] + incl - s;
    for (int i = 0; i < per; i++) {
        int idx = base + i;
        if (idx < n) {
            int v = g_cnt[idx];
            g_cur[idx] = run;
            run += v;
            g_cnt[idx] = 0;
        }
    }
}

// ---------------- launch 2: k_wt (64 rows/block, 4 col-slices) + scatter ----------------
__global__ __launch_bounds__(256) void k_wt_scatter(const float* __restrict__ X,
                                                    const void* __restrict__ ei,
                                                    int n, int E, int wtBlocks) {
    if ((int)blockIdx.x >= wtBlocks) {
        __shared__ int s32;
        if (threadIdx.x == 0) s32 = detect32(ei);
        __syncthreads();
        int e = (blockIdx.x - wtBlocks) * blockDim.x + threadIdx.x;
        if (e < E) {
            int pos = atomicAdd(&g_cur[dst_at(ei, e, s32)], 1);
            g_perm[pos] = e;
        }
        return;
    }
    extern __shared__ float sv[];
    float* Ms = sv;               // [128][132]  (M col-slice)
    float* As = sv + 128 * 132;   // [64][132]
    int tid = threadIdx.x;
    int b = blockIdx.x;
    int row0 = (b >> 2) * 64;
    int by = b & 3;

    for (int i = tid; i < 64 * DIM; i += 256) {
        int r = i >> 7, c = i & 127;
        int gr = row0 + r;
        As[r * 132 + c] = (gr < n) ? X[gr * DIM + c] : 0.f;
    }
    for (int i = tid; i < 128 * 128; i += 256) {
        int r = i >> 7, c = i & 127;
        Ms[r * 132 + c] = g_M[r * 512 + by * 128 + c];
    }
    __syncthreads();

    int cg = (tid & 31) * 4, rg = (tid >> 5) * 8;
    float acc[8][4] = {};
    #pragma unroll 4
    for (int d = 0; d < DIM; d++) {
        float4 w = *(float4*)&Ms[d * 132 + cg];
        #pragma unroll
        for (int rr = 0; rr < 8; rr++) {
            float a = As[(rg + rr) * 132 + d];
            acc[rr][0] += a * w.x; acc[rr][1] += a * w.y;
            acc[rr][2] += a * w.z; acc[rr][3] += a * w.w;
        }
    }
    float4 bb = *(const float4*)&g_B[by * 128 + cg];
    #pragma unroll
    for (int rr = 0; rr < 8; rr++) {
        int gr = row0 + rg + rr;
        if (gr < n) {
            float4 o = make_float4(acc[rr][0] + bb.x, acc[rr][1] + bb.y,
                                   acc[rr][2] + bb.z, acc[rr][3] + bb.w);
            *(float4*)&g_wt[(size_t)gr * 512 + by * 128 + cg] = o;
        }
    }
    // c-columns: only by==0 blocks; 256 threads = 64 nodes x 4 heads
    if (by == 0) {
        int nl = tid >> 2, h = tid & 3;
        int node = row0 + nl;
        float s = 0.f;
        #pragma unroll 8
        for (int c = 0; c < 128; c++) s += As[nl * 132 + c] * __ldg(&g_Mb[c * 4 + h]);
        if (node < n) g_c[node * 4 + h] = s + g_cb[h];
    }
}

// ---------------- launch 3 (PROFILED): k_edge — register streaming, depth-2 prefetch ----------------
__device__ __forceinline__ void flush_seg(int d, int lane, float4& a0, float4& a1,
                                          float4& a2, float4& a3, float4& ad) {
    float* S = g_S + (size_t)d * 512 + lane * 4;
    atomicAdd(S + 0,   a0.x); atomicAdd(S + 1,   a0.y); atomicAdd(S + 2,   a0.z); atomicAdd(S + 3,   a0.w);
    atomicAdd(S + 128, a1.x); atomicAdd(S + 129, a1.y); atomicAdd(S + 130, a1.z); atomicAdd(S + 131, a1.w);
    atomicAdd(S + 256, a2.x); atomicAdd(S + 257, a2.y); atomicAdd(S + 258, a2.z); atomicAdd(S + 259, a2.w);
    atomicAdd(S + 384, a3.x); atomicAdd(S + 385, a3.y); atomicAdd(S + 386, a3.z); atomicAdd(S + 387, a3.w);
    if (lane < 4) {
        float dv = (lane == 0) ? ad.x : (lane == 1) ? ad.y : (lane == 2) ? ad.z : ad.w;
        atomicAdd(&g_den[d * 4 + lane], dv);
    }
    a0 = a1 = a2 = a3 = make_float4(0.f, 0.f, 0.f, 0.f);
    ad = make_float4(0.f, 0.f, 0.f, 0.f);
}

__global__ __launch_bounds__(256) void k_edge(const float* __restrict__ ke,
                                              const float* __restrict__ ve,
                                              const void* __restrict__ ei, int E) {
    __shared__ int s32s;
    if (threadIdx.x == 0) s32s = detect32(ei);
    __syncthreads();
    int is32 = s32s;
    int lane = threadIdx.x & 31;
    int gw = (blockIdx.x * blockDim.x + threadIdx.x) >> 5;
    int base = gw * 64;
    if (base >= E) return;
    int cnt = min(64, E - base);

    int pe_l[2], d_l[2];
    #pragma unroll
    for (int j = 0; j < 2; j++) {
        int idx = base + j * 32 + lane;
        if (idx < E) {
            pe_l[j] = g_perm[idx];
            d_l[j] = dst_at(ei, pe_l[j], is32);
        } else { pe_l[j] = 0; d_l[j] = -1; }
    }

    const float4* keL = (const float4*)ke + lane;  // + pe*32 per row
    const float4* veL = (const float4*)ve + lane;

    // depth-2 software pipeline
    int i1 = (1 < cnt) ? 1 : 0;
    int p0 = __shfl_sync(0xffffffffu, pe_l[0], 0);
    int p1 = __shfl_sync(0xffffffffu, pe_l[i1 >> 5], i1 & 31);
    float4 k0 = __ldg(keL + (size_t)p0 * 32), v0 = __ldg(veL + (size_t)p0 * 32);
    float4 k1 = __ldg(keL + (size_t)p1 * 32), v1 = __ldg(veL + (size_t)p1 * 32);

    float4 a0 = make_float4(0.f, 0.f, 0.f, 0.f), a1 = a0, a2 = a0, a3 = a0, ad = a0;
    int prevd = -1;
    float4 wv0, wv1, wv2, wv3, cv;
    wv0 = wv1 = wv2 = wv3 = cv = a0;

    #pragma unroll 2
    for (int i = 0; i < cnt; i++) {
        int inx = (i + 2 < cnt) ? i + 2 : i;
        int pn = __shfl_sync(0xffffffffu, pe_l[inx >> 5], inx & 31);
        float4 k2 = __ldg(keL + (size_t)pn * 32);
        float4 v2 = __ldg(veL + (size_t)pn * 32);

        int d = __shfl_sync(0xffffffffu, d_l[i >> 5], i & 31);
        if (d != prevd) {
            if (prevd >= 0) flush_seg(prevd, lane, a0, a1, a2, a3, ad);
            const float4* bw = (const float4*)(g_wt + (size_t)d * 512) + lane;
            wv0 = __ldg(bw); wv1 = __ldg(bw + 32); wv2 = __ldg(bw + 64); wv3 = __ldg(bw + 96);
            cv = __ldg((const float4*)(g_c + d * 4));
            prevd = d;
        }
        float p0s = k0.x * wv0.x + k0.y * wv0.y + k0.z * wv0.z + k0.w * wv0.w;
        float p1s = k0.x * wv1.x + k0.y * wv1.y + k0.z * wv1.z + k0.w * wv1.w;
        float p2s = k0.x * wv2.x + k0.y * wv2.y + k0.z * wv2.z + k0.w * wv2.w;
        float p3s = k0.x * wv3.x + k0.y * wv3.y + k0.z * wv3.z + k0.w * wv3.w;
        #pragma unroll
        for (int off = 16; off; off >>= 1) {
            p0s += __shfl_xor_sync(0xffffffffu, p0s, off);
            p1s += __shfl_xor_sync(0xffffffffu, p1s, off);
            p2s += __shfl_xor_sync(0xffffffffu, p2s, off);
            p3s += __shfl_xor_sync(0xffffffffu, p3s, off);
        }
        float e0 = __expf(p0s + cv.x);
        float e1 = __expf(p1s + cv.y);
        float e2 = __expf(p2s + cv.z);
        float e3 = __expf(p3s + cv.w);
        a0.x += e0 * v0.x; a0.y += e0 * v0.y; a0.z += e0 * v0.z; a0.w += e0 * v0.w;
        a1.x += e1 * v0.x; a1.y += e1 * v0.y; a1.z += e1 * v0.z; a1.w += e1 * v0.w;
        a2.x += e2 * v0.x; a2.y += e2 * v0.y; a2.z += e2 * v0.z; a2.w += e2 * v0.w;
        a3.x += e3 * v0.x; a3.y += e3 * v0.y; a3.z += e3 * v0.z; a3.w += e3 * v0.w;
        ad.x += e0; ad.y += e1; ad.z += e2; ad.w += e3;
        k0 = k1; v0 = v1; k1 = k2; v1 = v2;
    }
    flush_seg(prevd, lane, a0, a1, a2, a3, ad);
}

// ---------------- launch 4: agg = (S @ Wv)/den + bv (+ self-clean) ----------------
__global__ __launch_bounds__(256) void k_vproj(const float* __restrict__ Wv,
                                               const float* __restrict__ bv, int n) {
    extern __shared__ float sq[];
    float* Ws = sq;               // [128][128]
    float* Ss = sq + 128 * 128;   // [32][4][136]
    int tid = threadIdx.x;
    int row0 = blockIdx.x * 32;
    for (int i = tid; i < DIM * DIM; i += 256) Ws[i] = Wv[i];
    for (int i = tid; i < 32 * 512; i += 256) {
        int nl = i >> 9, rest = i & 511;
        int h = rest >> 7, d = rest & 127;
        int gr = row0 + nl;
        float v = 0.f;
        if (gr < n) {
            size_t idx = (size_t)gr * 512 + rest;
            v = g_S[idx];
            g_S[idx] = 0.f;
        }
        Ss[nl * 544 + h * 136 + d] = v;
    }
    __syncthreads();
    int cg = (tid & 31) * 4, rg = (tid >> 5) * 4;
    int h = cg >> 5;
    float acc[4][4] = {};
    #pragma unroll 8
    for (int d = 0; d < DIM; d++) {
        float4 wv = *(float4*)&Ws[d * DIM + cg];
        float a0 = Ss[(rg + 0) * 544 + h * 136 + d];
        float a1 = Ss[(rg + 1) * 544 + h * 136 + d];
        float a2 = Ss[(rg + 2) * 544 + h * 136 + d];
        float a3 = Ss[(rg + 3) * 544 + h * 136 + d];
        acc[0][0] += a0 * wv.x; acc[0][1] += a0 * wv.y; acc[0][2] += a0 * wv.z; acc[0][3] += a0 * wv.w;
        acc[1][0] += a1 * wv.x; acc[1][1] += a1 * wv.y; acc[1][2] += a1 * wv.z; acc[1][3] += a1 * wv.w;
        acc[2][0] += a2 * wv.x; acc[2][1] += a2 * wv.y; acc[2][2] += a2 * wv.z; acc[2][3] += a2 * wv.w;
        acc[3][0] += a3 * wv.x; acc[3][1] += a3 * wv.y; acc[3][2] += a3 * wv.z; acc[3][3] += a3 * wv.w;
    }
    float4 bb = *(const float4*)&bv[cg];
    #pragma unroll
    for (int rr = 0; rr < 4; rr++) {
        int gr = row0 + rg + rr;
        if (gr < n) {
            float den = g_den[gr * HEADS + h];
            float4 o;
            if (den > 0.f) {
                float inv = 1.f / den;
                o = make_float4(acc[rr][0] * inv + bb.x, acc[rr][1] * inv + bb.y,
                                acc[rr][2] * inv + bb.z, acc[rr][3] * inv + bb.w);
            } else {
                o = make_float4(0.f, 0.f, 0.f, 0.f);
            }
            *(float4*)&g_agg[gr * DIM + cg] = o;
        }
    }
    __syncthreads();
    for (int i = tid; i < 32 * HEADS; i += 256) {
        int gr = row0 + (i >> 2);
        if (gr < n) g_den[gr * HEADS + (i & 3)] = 0.f;
    }
}

// ---------------- launch 5: out = agg @ Wo + bo ----------------
__global__ __launch_bounds__(256) void k_out(const float* __restrict__ W,
                                             const float* __restrict__ b,
                                             float* __restrict__ Y, int n) {
    extern __shared__ float so[];
    float* Ws = so;
    float* As = so + DIM * DIM;
    int tid = threadIdx.x;
    for (int i = tid; i < DIM * DIM; i += 256) Ws[i] = W[i];
    int row0 = blockIdx.x * 32;
    for (int i = tid; i < 32 * DIM; i += 256) {
        int r = i >> 7, c = i & 127;
        int gr = row0 + r;
        As[r * 132 + c] = (gr < n) ? g_agg[gr * DIM + c] : 0.f;
    }
    __syncthreads();
    int cg = (tid & 31) * 4, rg = (tid >> 5) * 4;
    float acc[4][4] = {};
    #pragma unroll 8
    for (int d = 0; d < DIM; d++) {
        float4 w = *(float4*)&Ws[d * DIM + cg];
        float a0 = As[(rg + 0) * 132 + d];
        float a1 = As[(rg + 1) * 132 + d];
        float a2 = As[(rg + 2) * 132 + d];
        float a3 = As[(rg + 3) * 132 + d];
        acc[0][0] += a0 * w.x; acc[0][1] += a0 * w.y; acc[0][2] += a0 * w.z; acc[0][3] += a0 * w.w;
        acc[1][0] += a1 * w.x; acc[1][1] += a1 * w.y; acc[1][2] += a1 * w.z; acc[1][3] += a1 * w.w;
        acc[2][0] += a2 * w.x; acc[2][1] += a2 * w.y; acc[2][2] += a2 * w.z; acc[2][3] += a2 * w.w;
        acc[3][0] += a3 * w.x; acc[3][1] += a3 * w.y; acc[3][2] += a3 * w.z; acc[3][3] += a3 * w.w;
    }
    float4 bb = *(const float4*)&b[cg];
    #pragma unroll
    for (int rr = 0; rr < 4; rr++) {
        int gr = row0 + rg + rr;
        if (gr < n) {
            float4 o = make_float4(acc[rr][0] + bb.x, acc[rr][1] + bb.y,
                                   acc[rr][2] + bb.z, acc[rr][3] + bb.w);
            *(float4*)&Y[gr * DIM + cg] = o;
        }
    }
}

extern "C" void kernel_launch(void* const* d_in, const int* in_sizes, int n_in,
                              void* d_out, int out_size) {
    const float* q_nodes = (const float*)d_in[0];
    const float* k_edges = (const float*)d_in[1];
    const float* v_edges = (const float*)d_in[2];
    const float* Wq = (const float*)d_in[3];
    const float* bq = (const float*)d_in[4];
    const float* Wk = (const float*)d_in[5];
    const float* bk = (const float*)d_in[6];
    const float* Wv = (const float*)d_in[7];
    const float* bv = (const float*)d_in[8];
    const float* Wo = (const float*)d_in[9];
    const float* bo = (const float*)d_in[10];
    const void*  ei = (const void*)d_in[11];

    int N = in_sizes[0] / DIM;
    int E = in_sizes[1] / DIM;

    const int smem_ph = (128 * 132 + 4 * 128) * (int)sizeof(float);   // 69632
    const int smem_ws = (192 * 132) * (int)sizeof(float);             // 101376
    const int smem_vp = (128 * 128 + 32 * 544) * (int)sizeof(float);  // 135168
    const int smem_out = (DIM * DIM + 32 * 132) * (int)sizeof(float); // 82432
    cudaFuncSetAttribute(k_prep_hist, cudaFuncAttributeMaxDynamicSharedMemorySize, smem_ph);
    cudaFuncSetAttribute(k_wt_scatter, cudaFuncAttributeMaxDynamicSharedMemorySize, smem_ws);
    cudaFuncSetAttribute(k_vproj, cudaFuncAttributeMaxDynamicSharedMemorySize, smem_vp);
    cudaFuncSetAttribute(k_out, cudaFuncAttributeMaxDynamicSharedMemorySize, smem_out);

    int nblk = (N + 31) / 32;
    int histBlocks = (E + 255) / 256;
    int wtBlocks = ((N + 63) / 64) * 4;
    int ewarps = (E + 63) / 64;
    int eblocks = (ewarps + 7) / 8;

    k_prep_hist<<<32 + histBlocks, 256, smem_ph>>>(Wq, bq, Wk, bk, ei, E);          // 0
    k_scan<<<1, 1024>>>(N);                                                          // 1
    k_wt_scatter<<<wtBlocks + histBlocks, 256, smem_ws>>>(q_nodes, ei, N, E, wtBlocks); // 2
    k_edge<<<eblocks, 256>>>(k_edges, v_edges, ei, E);                               // 3 (profiled)
    k_vproj<<<nblk, 256, smem_vp>>>(Wv, bv, N);                                      // 4
    k_out<<<nblk, 256, smem_out>>>(Wo, bo, (float*)d_out, N);                        // 5
}

// round 10
// speedup vs baseline: 1.4358x; 1.0667x over previous
#include <cuda_runtime.h>
#include <cstdint>
#include <math.h>

#define N_NODES 10000
#define E_EDGES 640000
#define DIM     128
#define HEADS   4

// device globals zero-init at load; consumers re-zero what they read.
__device__ float g_M[128 * 512];         // M[c][h*128+k], scale folded
__device__ float g_B[512];               // B[h*128+k], scale folded
__device__ float g_Mb[128 * 4];          // Mb[c][h], scale folded
__device__ float g_cb[4];                // scale folded
__device__ float g_wt[N_NODES * 512];    // w-tilde [n][h*128+k]
__device__ float g_c[N_NODES * HEADS];
__device__ float g_ex[E_EDGES * 4];      // exp(score) in PERM order (rewritten each call)
__device__ float g_S[N_NODES * 512];     // self-cleaned by k_vproj
__device__ float g_agg[N_NODES * DIM];
__device__ float g_den[N_NODES * HEADS]; // self-cleaned by k_vproj
__device__ int   g_cnt[N_NODES];         // self-cleaned by k_scan
__device__ int   g_cur[N_NODES];         // fully rewritten by k_scan
__device__ int   g_perm[E_EDGES];        // fully rewritten by scatter

__device__ __forceinline__ int detect32(const void* ei) {
    const long long* p = (const long long*)ei;
    long long x = 0;
    #pragma unroll
    for (int i = 0; i < 8; i++) x |= p[i];
    return (((unsigned long long)x) >> 32) != 0ull;
}
__device__ __forceinline__ int dst_at(const void* ei, int e, int is32) {
    return is32 ? ((const int*)ei)[e] : (int)((const long long*)ei)[e];
}

// ---------------- launch 0: prep (blocks [0,32)) + hist (rest); NO smem ----------------
__global__ __launch_bounds__(256) void k_hist_prep(const float* __restrict__ Wq,
                                                   const float* __restrict__ bq,
                                                   const float* __restrict__ Wk,
                                                   const float* __restrict__ bk,
                                                   const void* __restrict__ ei, int E) {
    const float scale = 0.17677669529663689f;  // 1/sqrt(32)
    int tid = threadIdx.x;
    if ((int)blockIdx.x >= 32) {
        __shared__ int s32;
        if (tid == 0) s32 = detect32(ei);
        __syncthreads();
        int e = (blockIdx.x - 32) * blockDim.x + tid;
        if (e < E) atomicAdd(&g_cnt[dst_at(ei, e, s32)], 1);
        return;
    }
    int b = blockIdx.x;
    int c = tid & 127, kp = tid >> 7;   // kp 0/1 -> k_local {2kp, 2kp+1}
    #pragma unroll
    for (int h = 0; h < 4; h++) {
        float wq[32];
        #pragma unroll
        for (int d4 = 0; d4 < 8; d4++) {
            float4 v = __ldg((const float4*)&Wq[c * 128 + h * 32 + d4 * 4]);
            wq[d4 * 4 + 0] = v.x; wq[d4 * 4 + 1] = v.y;
            wq[d4 * 4 + 2] = v.z; wq[d4 * 4 + 3] = v.w;
        }
        #pragma unroll
        for (int j = 0; j < 2; j++) {
            int kl = 2 * kp + j;
            float s = 0.f;
            #pragma unroll
            for (int d = 0; d < 32; d++)
                s += wq[d] * __ldg(&Wk[(b * 4 + kl) * 128 + h * 32 + d]);
            g_M[c * 512 + h * 128 + b * 4 + kl] = s * scale;
        }
    }
    if (tid < 16) {
        int kl = tid >> 2, h = tid & 3;
        float s = 0.f;
        #pragma unroll
        for (int d = 0; d < 32; d++)
            s += __ldg(&bq[h * 32 + d]) * __ldg(&Wk[(b * 4 + kl) * 128 + h * 32 + d]);
        g_B[h * 128 + b * 4 + kl] = s * scale;
    }
    if (b == 0) {
        int hp = tid >> 7;
        #pragma unroll
        for (int j = 0; j < 2; j++) {
            int h = 2 * hp + j;
            float s = 0.f;
            #pragma unroll
            for (int d = 0; d < 32; d++)
                s += __ldg(&Wq[c * 128 + h * 32 + d]) * __ldg(&bk[h * 32 + d]);
            g_Mb[c * 4 + h] = s * scale;
        }
        if (tid < 4) {
            float s = 0.f;
            #pragma unroll
            for (int d = 0; d < 32; d++) s += __ldg(&bq[tid * 32 + d]) * __ldg(&bk[tid * 32 + d]);
            g_cb[tid] = s * scale;
        }
    }
}

// ---------------- launch 1: scan (+ self-clean g_cnt) ----------------
__global__ __launch_bounds__(1024) void k_scan(int n) {
    __shared__ int ws[32];
    int t = threadIdx.x, lane = t & 31, wd = t >> 5;
    int per = (n + 1023) / 1024;
    int base = t * per;
    int s = 0;
    for (int i = 0; i < per; i++) {
        int idx = base + i;
        if (idx < n) s += g_cnt[idx];
    }
    int incl = s;
    #pragma unroll
    for (int off = 1; off < 32; off <<= 1) {
        int y = __shfl_up_sync(0xffffffffu, incl, off);
        if (lane >= off) incl += y;
    }
    if (lane == 31) ws[wd] = incl;
    __syncthreads();
    if (wd == 0) {
        int v = ws[lane];
        int iv = v;
        #pragma unroll
        for (int off = 1; off < 32; off <<= 1) {
            int y = __shfl_up_sync(0xffffffffu, iv, off);
            if (lane >= off) iv += y;
        }
        ws[lane] = iv - v;
    }
    __syncthreads();
    int run = ws[wd] + incl - s;
    for (int i = 0; i < per; i++) {
        int idx = base + i;
        if (idx < n) {
            int v = g_cnt[idx];
            g_cur[idx] = run;
            run += v;
            g_cnt[idx] = 0;
        }
    }
}

// ---------------- launch 2: k_wt (smem = As only) + scatter ----------------
__global__ __launch_bounds__(256) void k_wt_scatter(const float* __restrict__ X,
                                                    const void* __restrict__ ei,
                                                    int n, int E, int wtBlocks) {
    if ((int)blockIdx.x >= wtBlocks) {
        __shared__ int s32;
        if (threadIdx.x == 0) s32 = detect32(ei);
        __syncthreads();
        int e = (blockIdx.x - wtBlocks) * blockDim.x + threadIdx.x;
        if (e < E) {
            int pos = atomicAdd(&g_cur[dst_at(ei, e, s32)], 1);
            g_perm[pos] = e;
        }
        return;
    }
    extern __shared__ float sv[];
    float* As = sv;               // [64][132]
    int tid = threadIdx.x;
    int b = blockIdx.x;
    int row0 = (b >> 2) * 64;
    int by = b & 3;

    for (int i = tid; i < 64 * DIM; i += 256) {
        int r = i >> 7, c = i & 127;
        int gr = row0 + r;
        As[r * 132 + c] = (gr < n) ? X[gr * DIM + c] : 0.f;
    }
    __syncthreads();

    int cg = (tid & 31) * 4, rg = (tid >> 5) * 8;
    float acc[8][4] = {};
    #pragma unroll 4
    for (int d = 0; d < DIM; d++) {
        float4 w = __ldg((const float4*)&g_M[d * 512 + by * 128 + cg]);
        #pragma unroll
        for (int rr = 0; rr < 8; rr++) {
            float a = As[(rg + rr) * 132 + d];
            acc[rr][0] += a * w.x; acc[rr][1] += a * w.y;
            acc[rr][2] += a * w.z; acc[rr][3] += a * w.w;
        }
    }
    float4 bb = __ldg((const float4*)&g_B[by * 128 + cg]);
    #pragma unroll
    for (int rr = 0; rr < 8; rr++) {
        int gr = row0 + rg + rr;
        if (gr < n) {
            float4 o = make_float4(acc[rr][0] + bb.x, acc[rr][1] + bb.y,
                                   acc[rr][2] + bb.z, acc[rr][3] + bb.w);
            *(float4*)&g_wt[(size_t)gr * 512 + by * 128 + cg] = o;
        }
    }
    if (by == 0) {
        int nl = tid >> 2, h = tid & 3;
        int node = row0 + nl;
        float s = 0.f;
        #pragma unroll 8
        for (int c = 0; c < 128; c++) s += As[nl * 132 + c] * __ldg(&g_Mb[c * 4 + h]);
        if (node < n) g_c[node * 4 + h] = s + g_cb[h];
    }
}

// ---------------- launch 3 (PROFILED): k_score — scores -> g_ex (perm order) ----------------
__global__ __launch_bounds__(256) void k_score(const float* __restrict__ ke,
                                               const void* __restrict__ ei, int E) {
    __shared__ int s32s;
    if (threadIdx.x == 0) s32s = detect32(ei);
    __syncthreads();
    int is32 = s32s;
    int lane = threadIdx.x & 31;
    int gw = (blockIdx.x * blockDim.x + threadIdx.x) >> 5;
    int base = gw * 64;
    if (base >= E) return;
    int cnt = min(64, E - base);

    int pe_l[2], d_l[2];
    #pragma unroll
    for (int j = 0; j < 2; j++) {
        int idx = base + j * 32 + lane;
        if (idx < E) {
            pe_l[j] = g_perm[idx];
            d_l[j] = dst_at(ei, pe_l[j], is32);
        } else { pe_l[j] = 0; d_l[j] = -1; }
    }

    const float4* keL = (const float4*)ke + lane;
    int i1 = (1 < cnt) ? 1 : 0;
    int p0 = __shfl_sync(0xffffffffu, pe_l[0], 0);
    int p1 = __shfl_sync(0xffffffffu, pe_l[i1 >> 5], i1 & 31);
    float4 k0 = __ldg(keL + (size_t)p0 * 32);
    float4 k1 = __ldg(keL + (size_t)p1 * 32);

    int prevd = -1;
    float4 wv0, wv1, wv2, wv3, cv;
    wv0 = wv1 = wv2 = wv3 = cv = make_float4(0.f, 0.f, 0.f, 0.f);

    #pragma unroll 2
    for (int i = 0; i < cnt; i++) {
        int inx = (i + 2 < cnt) ? i + 2 : i;
        int pn = __shfl_sync(0xffffffffu, pe_l[inx >> 5], inx & 31);
        float4 k2 = __ldg(keL + (size_t)pn * 32);

        int d = __shfl_sync(0xffffffffu, d_l[i >> 5], i & 31);
        if (d != prevd) {
            const float4* bw = (const float4*)(g_wt + (size_t)d * 512) + lane;
            wv0 = __ldg(bw); wv1 = __ldg(bw + 32); wv2 = __ldg(bw + 64); wv3 = __ldg(bw + 96);
            cv = __ldg((const float4*)(g_c + d * 4));
            prevd = d;
        }
        float q0 = k0.x * wv0.x + k0.y * wv0.y + k0.z * wv0.z + k0.w * wv0.w;
        float q1 = k0.x * wv1.x + k0.y * wv1.y + k0.z * wv1.z + k0.w * wv1.w;
        float q2 = k0.x * wv2.x + k0.y * wv2.y + k0.z * wv2.z + k0.w * wv2.w;
        float q3 = k0.x * wv3.x + k0.y * wv3.y + k0.z * wv3.z + k0.w * wv3.w;
        #pragma unroll
        for (int off = 16; off; off >>= 1) {
            q0 += __shfl_xor_sync(0xffffffffu, q0, off);
            q1 += __shfl_xor_sync(0xffffffffu, q1, off);
            q2 += __shfl_xor_sync(0xffffffffu, q2, off);
            q3 += __shfl_xor_sync(0xffffffffu, q3, off);
        }
        if (lane < 4) {
            float p = (lane == 0) ? q0 : (lane == 1) ? q1 : (lane == 2) ? q2 : q3;
            float cc = (lane == 0) ? cv.x : (lane == 1) ? cv.y : (lane == 2) ? cv.z : cv.w;
            g_ex[(size_t)(base + i) * 4 + lane] = __expf(p + cc);
        }
        k0 = k1; k1 = k2;
    }
}

// ---------------- launch 4: k_aggr — v aggregation with precomputed ex ----------------
__device__ __forceinline__ void flush_seg(int d, int lane, float4& a0, float4& a1,
                                          float4& a2, float4& a3, float4& ad) {
    float* S = g_S + (size_t)d * 512 + lane * 4;
    atomicAdd(S + 0,   a0.x); atomicAdd(S + 1,   a0.y); atomicAdd(S + 2,   a0.z); atomicAdd(S + 3,   a0.w);
    atomicAdd(S + 128, a1.x); atomicAdd(S + 129, a1.y); atomicAdd(S + 130, a1.z); atomicAdd(S + 131, a1.w);
    atomicAdd(S + 256, a2.x); atomicAdd(S + 257, a2.y); atomicAdd(S + 258, a2.z); atomicAdd(S + 259, a2.w);
    atomicAdd(S + 384, a3.x); atomicAdd(S + 385, a3.y); atomicAdd(S + 386, a3.z); atomicAdd(S + 387, a3.w);
    if (lane < 4) {
        float dv = (lane == 0) ? ad.x : (lane == 1) ? ad.y : (lane == 2) ? ad.z : ad.w;
        atomicAdd(&g_den[d * 4 + lane], dv);
    }
    a0 = a1 = a2 = a3 = make_float4(0.f, 0.f, 0.f, 0.f);
    ad = make_float4(0.f, 0.f, 0.f, 0.f);
}

__global__ __launch_bounds__(256) void k_aggr(const float* __restrict__ ve,
                                              const void* __restrict__ ei, int E) {
    __shared__ int s32s;
    if (threadIdx.x == 0) s32s = detect32(ei);
    __syncthreads();
    int is32 = s32s;
    int lane = threadIdx.x & 31;
    int gw = (blockIdx.x * blockDim.x + threadIdx.x) >> 5;
    int base = gw * 64;
    if (base >= E) return;
    int cnt = min(64, E - base);

    int pe_l[2], d_l[2];
    #pragma unroll
    for (int j = 0; j < 2; j++) {
        int idx = base + j * 32 + lane;
        if (idx < E) {
            pe_l[j] = g_perm[idx];
            d_l[j] = dst_at(ei, pe_l[j], is32);
        } else { pe_l[j] = 0; d_l[j] = -1; }
    }

    const float4* veL = (const float4*)ve + lane;
    int i1 = (1 < cnt) ? 1 : 0;
    int p0 = __shfl_sync(0xffffffffu, pe_l[0], 0);
    int p1 = __shfl_sync(0xffffffffu, pe_l[i1 >> 5], i1 & 31);
    float4 v0 = __ldg(veL + (size_t)p0 * 32);
    float4 v1 = __ldg(veL + (size_t)p1 * 32);
    float4 e0 = __ldg((const float4*)(g_ex + (size_t)base * 4));
    float4 e1 = __ldg((const float4*)(g_ex + (size_t)(base + i1) * 4));

    float4 a0 = make_float4(0.f, 0.f, 0.f, 0.f), a1 = a0, a2 = a0, a3 = a0, ad = a0;
    int prevd = -1;

    #pragma unroll 2
    for (int i = 0; i < cnt; i++) {
        int inx = (i + 2 < cnt) ? i + 2 : i;
        int pn = __shfl_sync(0xffffffffu, pe_l[inx >> 5], inx & 31);
        float4 v2 = __ldg(veL + (size_t)pn * 32);
        float4 e2 = __ldg((const float4*)(g_ex + (size_t)(base + inx) * 4));

        int d = __shfl_sync(0xffffffffu, d_l[i >> 5], i & 31);
        if (d != prevd) {
            if (prevd >= 0) flush_seg(prevd, lane, a0, a1, a2, a3, ad);
            prevd = d;
        }
        a0.x += e0.x * v0.x; a0.y += e0.x * v0.y; a0.z += e0.x * v0.z; a0.w += e0.x * v0.w;
        a1.x += e0.y * v0.x; a1.y += e0.y * v0.y; a1.z += e0.y * v0.z; a1.w += e0.y * v0.w;
        a2.x += e0.z * v0.x; a2.y += e0.z * v0.y; a2.z += e0.z * v0.z; a2.w += e0.z * v0.w;
        a3.x += e0.w * v0.x; a3.y += e0.w * v0.y; a3.z += e0.w * v0.z; a3.w += e0.w * v0.w;
        ad.x += e0.x; ad.y += e0.y; ad.z += e0.z; ad.w += e0.w;
        v0 = v1; v1 = v2; e0 = e1; e1 = e2;
    }
    flush_seg(prevd, lane, a0, a1, a2, a3, ad);
}

// ---------------- launch 5: agg = (S @ Wv)/den + bv (+ self-clean; smem = Ss only) ----------------
__global__ __launch_bounds__(256) void k_vproj(const float* __restrict__ Wv,
                                               const float* __restrict__ bv, int n) {
    extern __shared__ float sq[];
    float* Ss = sq;               // [32][4][136]
    int tid = threadIdx.x;
    int row0 = blockIdx.x * 32;
    for (int i = tid; i < 32 * 512; i += 256) {
        int nl = i >> 9, rest = i & 511;
        int h = rest >> 7, d = rest & 127;
        int gr = row0 + nl;
        float v = 0.f;
        if (gr < n) {
            size_t idx = (size_t)gr * 512 + rest;
            v = g_S[idx];
            g_S[idx] = 0.f;
        }
        Ss[nl * 544 + h * 136 + d] = v;
    }
    __syncthreads();
    int cg = (tid & 31) * 4, rg = (tid >> 5) * 4;
    int h = cg >> 5;
    float acc[4][4] = {};
    #pragma unroll 8
    for (int d = 0; d < DIM; d++) {
        float4 wv = __ldg((const float4*)&Wv[d * DIM + cg]);
        float a0 = Ss[(rg + 0) * 544 + h * 136 + d];
        float a1 = Ss[(rg + 1) * 544 + h * 136 + d];
        float a2 = Ss[(rg + 2) * 544 + h * 136 + d];
        float a3 = Ss[(rg + 3) * 544 + h * 136 + d];
        acc[0][0] += a0 * wv.x; acc[0][1] += a0 * wv.y; acc[0][2] += a0 * wv.z; acc[0][3] += a0 * wv.w;
        acc[1][0] += a1 * wv.x; acc[1][1] += a1 * wv.y; acc[1][2] += a1 * wv.z; acc[1][3] += a1 * wv.w;
        acc[2][0] += a2 * wv.x; acc[2][1] += a2 * wv.y; acc[2][2] += a2 * wv.z; acc[2][3] += a2 * wv.w;
        acc[3][0] += a3 * wv.x; acc[3][1] += a3 * wv.y; acc[3][2] += a3 * wv.z; acc[3][3] += a3 * wv.w;
    }
    float4 bb = __ldg((const float4*)&bv[cg]);
    #pragma unroll
    for (int rr = 0; rr < 4; rr++) {
        int gr = row0 + rg + rr;
        if (gr < n) {
            float den = g_den[gr * HEADS + h];
            float4 o;
            if (den > 0.f) {
                float inv = 1.f / den;
                o = make_float4(acc[rr][0] * inv + bb.x, acc[rr][1] * inv + bb.y,
                                acc[rr][2] * inv + bb.z, acc[rr][3] * inv + bb.w);
            } else {
                o = make_float4(0.f, 0.f, 0.f, 0.f);
            }
            *(float4*)&g_agg[gr * DIM + cg] = o;
        }
    }
    __syncthreads();
    for (int i = tid; i < 32 * HEADS; i += 256) {
        int gr = row0 + (i >> 2);
        if (gr < n) g_den[gr * HEADS + (i & 3)] = 0.f;
    }
}

// ---------------- launch 6: out = agg @ Wo + bo (smem = As only) ----------------
__global__ __launch_bounds__(256) void k_out(const float* __restrict__ W,
                                             const float* __restrict__ b,
                                             float* __restrict__ Y, int n) {
    extern __shared__ float so[];
    float* As = so;               // [32][132]
    int tid = threadIdx.x;
    int row0 = blockIdx.x * 32;
    for (int i = tid; i < 32 * DIM; i += 256) {
        int r = i >> 7, c = i & 127;
        int gr = row0 + r;
        As[r * 132 + c] = (gr < n) ? g_agg[gr * DIM + c] : 0.f;
    }
    __syncthreads();
    int cg = (tid & 31) * 4, rg = (tid >> 5) * 4;
    float acc[4][4] = {};
    #pragma unroll 8
    for (int d = 0; d < DIM; d++) {
        float4 w = __ldg((const float4*)&W[d * DIM + cg]);
        float a0 = As[(rg + 0) * 132 + d];
        float a1 = As[(rg + 1) * 132 + d];
        float a2 = As[(rg + 2) * 132 + d];
        float a3 = As[(rg + 3) * 132 + d];
        acc[0][0] += a0 * w.x; acc[0][1] += a0 * w.y; acc[0][2] += a0 * w.z; acc[0][3] += a0 * w.w;
        acc[1][0] += a1 * w.x; acc[1][1] += a1 * w.y; acc[1][2] += a1 * w.z; acc[1][3] += a1 * w.w;
        acc[2][0] += a2 * w.x; acc[2][1] += a2 * w.y; acc[2][2] += a2 * w.z; acc[2][3] += a2 * w.w;
        acc[3][0] += a3 * w.x; acc[3][1] += a3 * w.y; acc[3][2] += a3 * w.z; acc[3][3] += a3 * w.w;
    }
    float4 bb = __ldg((const float4*)&b[cg]);
    #pragma unroll
    for (int rr = 0; rr < 4; rr++) {
        int gr = row0 + rg + rr;
        if (gr < n) {
            float4 o = make_float4(acc[rr][0] + bb.x, acc[rr][1] + bb.y,
                                   acc[rr][2] + bb.z, acc[rr][3] + bb.w);
            *(float4*)&Y[gr * DIM + cg] = o;
        }
    }
}

extern "C" void kernel_launch(void* const* d_in, const int* in_sizes, int n_in,
                              void* d_out, int out_size) {
    const float* q_nodes = (const float*)d_in[0];
    const float* k_edges = (const float*)d_in[1];
    const float* v_edges = (const float*)d_in[2];
    const float* Wq = (const float*)d_in[3];
    const float* bq = (const float*)d_in[4];
    const float* Wk = (const float*)d_in[5];
    const float* bk = (const float*)d_in[6];
    const float* Wv = (const float*)d_in[7];
    const float* bv = (const float*)d_in[8];
    const float* Wo = (const float*)d_in[9];
    const float* bo = (const float*)d_in[10];
    const void*  ei = (const void*)d_in[11];

    int N = in_sizes[0] / DIM;
    int E = in_sizes[1] / DIM;

    const int smem_ws  = 64 * 132 * (int)sizeof(float);   // 33792
    const int smem_vp  = 32 * 544 * (int)sizeof(float);   // 69632
    const int smem_out = 32 * 132 * (int)sizeof(float);   // 16896
    cudaFuncSetAttribute(k_wt_scatter, cudaFuncAttributeMaxDynamicSharedMemorySize, smem_ws);
    cudaFuncSetAttribute(k_vproj, cudaFuncAttributeMaxDynamicSharedMemorySize, smem_vp);
    cudaFuncSetAttribute(k_out, cudaFuncAttributeMaxDynamicSharedMemorySize, smem_out);

    int nblk = (N + 31) / 32;
    int histBlocks = (E + 255) / 256;
    int wtBlocks = ((N + 63) / 64) * 4;
    int ewarps = (E + 63) / 64;
    int eblocks = (ewarps + 7) / 8;

    k_hist_prep<<<32 + histBlocks, 256>>>(Wq, bq, Wk, bk, ei, E);                        // 0
    k_scan<<<1, 1024>>>(N);                                                              // 1
    k_wt_scatter<<<wtBlocks + histBlocks, 256, smem_ws>>>(q_nodes, ei, N, E, wtBlocks);  // 2
    k_score<<<eblocks, 256>>>(k_edges, ei, E);                                           // 3 (profiled)
    k_aggr<<<eblocks, 256>>>(v_edges, ei, E);                                            // 4
    k_vproj<<<nblk, 256, smem_vp>>>(Wv, bv, N);                                          // 5
    k_out<<<nblk, 256, smem_out>>>(Wo, bo, (float*)d_out, N);                            // 6
}